// round 1
// baseline (speedup 1.0000x reference)
#include <cuda_runtime.h>
#include <math.h>
#include <stdint.h>

#define NHYP 4096
#define NPREM 4096
#define DIM 512
#define BD 768
#define NHEAD 4
#define ATND 128
#define NB 32
#define FEAT (DIM + BD)   // 1280

// ---------------- scratch (module-load allocated, not runtime alloc) ----------------
__device__ float g_Qp[(size_t)NHEAD * NHYP * ATND];     // [h][n][d]   8 MB
__device__ float g_Kp[(size_t)NHEAD * NPREM * ATND];    // [h][m][d]   8 MB
__device__ float g_V[(size_t)NPREM * BD];               // [m][768]   12 MB
__device__ float g_S[(size_t)NHEAD * NHYP * NPREM];     // [h][n][m] 256 MB
__device__ float g_att[(size_t)NHYP * BD];              // 12 MB
__device__ float g_feats[(size_t)NHYP * FEAT];          // 20 MB
__device__ float g_h1[(size_t)NHYP * 256];              // 4 MB
__device__ float g_h2[(size_t)NHYP * 128];              // 2 MB
__device__ int   g_bp[NPREM];
__device__ int   g_bh[NHYP];

// ---------------- batch id dtype detect + convert ----------------
// jax code does .astype(jnp.int64); with x64 disabled that is silently int32.
// Detect by looking at odd int32 words in the back half: int64 (values<2^32)
// has zero high words there; int32 sorted values there are ~16 (nonzero).
__global__ void conv_batch(const void* bpr, const void* bhr, int n) {
    __shared__ int s_is64;
    if (threadIdx.x == 0) {
        const int* w = (const int*)bhr;
        int z = 0;
        for (int i = 0; i < 32; i++) {
            int idx = n / 2 + 2 * i + 1;   // odd word index, within n words
            if (w[idx] == 0) z++;
        }
        s_is64 = (z > 16) ? 1 : 0;
    }
    __syncthreads();
    int is64 = s_is64;
    const int* bp32 = (const int*)bpr;
    const int* bh32 = (const int*)bhr;
    for (int i = threadIdx.x; i < n; i += blockDim.x) {
        g_bp[i] = is64 ? bp32[2 * i] : bp32[i];
        g_bh[i] = is64 ? bh32[2 * i] : bh32[i];
    }
}

// ---------------- generic 128x128x8 NN SGEMM ----------------
// EPI: 0 = plain (+bias if nonnull), 1 = permuted q/k store (+bias), 2 = gelu (+bias)
template <int EPI>
__global__ __launch_bounds__(256) void sgemm_nn(
    const float* __restrict__ A, const float* __restrict__ B,
    const float* __restrict__ bias, float* __restrict__ C,
    int M, int N, int K)
{
    __shared__ float As[8][128];
    __shared__ float Bs[8][128];
    int tid = threadIdx.x;
    int i0 = blockIdx.y * 128;
    int j0 = blockIdx.x * 128;
    int ty = tid >> 4, tx = tid & 15;

    int ar = tid >> 1;            // 0..127
    int ac = (tid & 1) * 4;       // 0 / 4
    int br = tid >> 5;            // 0..7
    int bc = (tid & 31) * 4;      // 0..124

    const float* Ag = A + (size_t)(i0 + ar) * K + ac;
    const float* Bg = B + (size_t)br * N + j0 + bc;

    float acc[8][8];
#pragma unroll
    for (int i = 0; i < 8; i++)
#pragma unroll
        for (int j = 0; j < 8; j++) acc[i][j] = 0.f;

    for (int k0 = 0; k0 < K; k0 += 8) {
        float4 av = *(const float4*)(Ag + k0);
        float4 bv = *(const float4*)(Bg + (size_t)k0 * N);
        As[ac + 0][ar] = av.x; As[ac + 1][ar] = av.y;
        As[ac + 2][ar] = av.z; As[ac + 3][ar] = av.w;
        *(float4*)&Bs[br][bc] = bv;
        __syncthreads();
#pragma unroll
        for (int kk = 0; kk < 8; kk++) {
            float a[8], b[8];
            *(float4*)&a[0] = *(const float4*)&As[kk][ty * 8];
            *(float4*)&a[4] = *(const float4*)&As[kk][ty * 8 + 4];
            *(float4*)&b[0] = *(const float4*)&Bs[kk][tx * 8];
            *(float4*)&b[4] = *(const float4*)&Bs[kk][tx * 8 + 4];
#pragma unroll
            for (int i = 0; i < 8; i++)
#pragma unroll
                for (int j = 0; j < 8; j++) acc[i][j] = fmaf(a[i], b[j], acc[i][j]);
        }
        __syncthreads();
    }

#pragma unroll
    for (int i = 0; i < 8; i++) {
        int rg = i0 + ty * 8 + i;
#pragma unroll
        for (int j = 0; j < 8; j++) {
            int cg = j0 + tx * 8 + j;
            float v = acc[i][j];
            if (bias) v += bias[cg];
            if (EPI == 1) {
                int hh = cg & 3, dd = cg >> 2;
                C[((size_t)hh * M + rg) * ATND + dd] = v;
            } else {
                if (EPI == 2) v = 0.5f * v * (1.0f + erff(v * 0.70710678118654752f));
                C[(size_t)rg * N + cg] = v;
            }
        }
    }
}

// ---------------- per-head NT GEMM: S[h][n][m] = scale * Qp[h][n,:] . Kp[h][m,:] ----------------
__global__ __launch_bounds__(256) void sgemm_nt_logits(
    const float* __restrict__ Qp, const float* __restrict__ Kp, float* __restrict__ S)
{
    const float* A = Qp + (size_t)blockIdx.z * NHYP * ATND;
    const float* B = Kp + (size_t)blockIdx.z * NPREM * ATND;
    float* C = S + (size_t)blockIdx.z * NHYP * NPREM;

    __shared__ float As[8][128];
    __shared__ float Bs[8][128];
    int tid = threadIdx.x;
    int i0 = blockIdx.y * 128;
    int j0 = blockIdx.x * 128;
    int ty = tid >> 4, tx = tid & 15;
    int r = tid >> 1, c = (tid & 1) * 4;

    const float* Ag = A + (size_t)(i0 + r) * ATND + c;
    const float* Bg = B + (size_t)(j0 + r) * ATND + c;

    float acc[8][8];
#pragma unroll
    for (int i = 0; i < 8; i++)
#pragma unroll
        for (int j = 0; j < 8; j++) acc[i][j] = 0.f;

    for (int k0 = 0; k0 < ATND; k0 += 8) {
        float4 av = *(const float4*)(Ag + k0);
        float4 bv = *(const float4*)(Bg + k0);
        As[c + 0][r] = av.x; As[c + 1][r] = av.y; As[c + 2][r] = av.z; As[c + 3][r] = av.w;
        Bs[c + 0][r] = bv.x; Bs[c + 1][r] = bv.y; Bs[c + 2][r] = bv.z; Bs[c + 3][r] = bv.w;
        __syncthreads();
#pragma unroll
        for (int kk = 0; kk < 8; kk++) {
            float a[8], b[8];
            *(float4*)&a[0] = *(const float4*)&As[kk][ty * 8];
            *(float4*)&a[4] = *(const float4*)&As[kk][ty * 8 + 4];
            *(float4*)&b[0] = *(const float4*)&Bs[kk][tx * 8];
            *(float4*)&b[4] = *(const float4*)&Bs[kk][tx * 8 + 4];
#pragma unroll
            for (int i = 0; i < 8; i++)
#pragma unroll
                for (int j = 0; j < 8; j++) acc[i][j] = fmaf(a[i], b[j], acc[i][j]);
        }
        __syncthreads();
    }

    const float scale = 0.08838834764831845f;  // 1/sqrt(128)
#pragma unroll
    for (int i = 0; i < 8; i++) {
        int rg = i0 + ty * 8 + i;
#pragma unroll
        for (int j = 0; j < 8; j++) {
            int cg = j0 + tx * 8 + j;
            C[(size_t)rg * NPREM + cg] = acc[i][j] * scale;
        }
    }
}

// ---------------- masked softmax over m, in place ----------------
__device__ __forceinline__ float warpMax(float v) {
#pragma unroll
    for (int o = 16; o; o >>= 1) v = fmaxf(v, __shfl_xor_sync(0xffffffffu, v, o));
    return v;
}
__device__ __forceinline__ float warpSum(float v) {
#pragma unroll
    for (int o = 16; o; o >>= 1) v += __shfl_xor_sync(0xffffffffu, v, o);
    return v;
}

__global__ __launch_bounds__(256) void softmax_mask(float* __restrict__ S)
{
    int n = blockIdx.x;
    int h = blockIdx.y;
    float* row = S + ((size_t)h * NHYP + n) * NPREM;
    int tid = threadIdx.x;
    int myb = g_bh[n];

    float v[16];
    float mx = -INFINITY;
#pragma unroll
    for (int t = 0; t < 16; t++) {
        int m = t * 256 + tid;
        float x = row[m];
        if (g_bp[m] == myb) x = -1e10f;   // faithful to reference mask
        v[t] = x;
        mx = fmaxf(mx, x);
    }
    __shared__ float sred[8];
    __shared__ float sbc;
    float wm = warpMax(mx);
    int lane = tid & 31, wid = tid >> 5;
    if (lane == 0) sred[wid] = wm;
    __syncthreads();
    if (wid == 0) {
        float x = (lane < 8) ? sred[lane] : -INFINITY;
        x = warpMax(x);
        if (lane == 0) sbc = x;
    }
    __syncthreads();
    mx = sbc;

    float s = 0.f;
#pragma unroll
    for (int t = 0; t < 16; t++) {
        float e = expf(v[t] - mx);
        v[t] = e;
        s += e;
    }
    float ws = warpSum(s);
    if (lane == 0) sred[wid] = ws;
    __syncthreads();
    if (wid == 0) {
        float x = (lane < 8) ? sred[lane] : 0.f;
        x = warpSum(x);
        if (lane == 0) sbc = x;
    }
    __syncthreads();
    float inv = 1.0f / sbc;
#pragma unroll
    for (int t = 0; t < 16; t++) row[t * 256 + tid] = v[t] * inv;
}

// ---------------- attended = P[h] @ V[h]   (BM=128, BN=192, BK=8, 512 thr, 8x6 microtile) ----------------
__global__ __launch_bounds__(512) void sgemm_att(
    const float* __restrict__ S, const float* __restrict__ V, float* __restrict__ Att)
{
    int h = blockIdx.z;
    const float* A = S + (size_t)h * NHYP * NPREM + (size_t)blockIdx.y * 128 * NPREM;
    const float* B = V + h * 192;

    __shared__ float As[8][128];
    __shared__ float Bs[8][192];
    int tid = threadIdx.x;
    int tr = tid >> 5;        // 0..15 -> rows tr*8..
    int tc = tid & 31;        // 0..31 -> cols tc*6..

    float acc[8][6];
#pragma unroll
    for (int i = 0; i < 8; i++)
#pragma unroll
        for (int j = 0; j < 6; j++) acc[i][j] = 0.f;

    for (int k0 = 0; k0 < NPREM; k0 += 8) {
#pragma unroll
        for (int idx = tid; idx < 1024; idx += 512) {
            int rr = idx >> 3, cc = idx & 7;
            As[cc][rr] = A[(size_t)rr * NPREM + k0 + cc];
        }
#pragma unroll
        for (int idx = tid; idx < 1536; idx += 512) {
            int rr = idx / 192, cc = idx % 192;
            Bs[rr][cc] = B[(size_t)(k0 + rr) * BD + cc];
        }
        __syncthreads();
#pragma unroll
        for (int kk = 0; kk < 8; kk++) {
            float a[8], b[6];
            *(float4*)&a[0] = *(const float4*)&As[kk][tr * 8];
            *(float4*)&a[4] = *(const float4*)&As[kk][tr * 8 + 4];
#pragma unroll
            for (int j = 0; j < 6; j++) b[j] = Bs[kk][tc * 6 + j];
#pragma unroll
            for (int i = 0; i < 8; i++)
#pragma unroll
                for (int j = 0; j < 6; j++) acc[i][j] = fmaf(a[i], b[j], acc[i][j]);
        }
        __syncthreads();
    }

#pragma unroll
    for (int i = 0; i < 8; i++) {
        int rg = blockIdx.y * 128 + tr * 8 + i;
#pragma unroll
        for (int j = 0; j < 6; j++) {
            Att[(size_t)rg * BD + h * 192 + tc * 6 + j] = acc[i][j];
        }
    }
}

// ---------------- feats = concat(ctx_h, lhs_h - attended) ----------------
__global__ void build_feats(const float* __restrict__ ctx_h, const float* __restrict__ lhs_h)
{
    size_t idx = (size_t)blockIdx.x * blockDim.x + threadIdx.x;
    if (idx >= (size_t)NHYP * FEAT) return;
    int n = (int)(idx / FEAT);
    int j = (int)(idx % FEAT);
    float v;
    if (j < DIM) v = ctx_h[(size_t)n * DIM + j];
    else {
        int jj = j - DIM;
        v = lhs_h[(size_t)n * BD + jj] - g_att[(size_t)n * BD + jj];
    }
    g_feats[idx] = v;
}

// ---------------- layernorm(128) in place ----------------
__global__ __launch_bounds__(128) void layernorm_inplace(
    float* __restrict__ X, const float* __restrict__ gw, const float* __restrict__ gb)
{
    int n = blockIdx.x;
    int d = threadIdx.x;
    float v = X[(size_t)n * 128 + d];
    __shared__ float sred[4];
    __shared__ float sbc;
    int lane = d & 31, wid = d >> 5;

    float s = warpSum(v);
    if (lane == 0) sred[wid] = s;
    __syncthreads();
    if (wid == 0) {
        float x = (lane < 4) ? sred[lane] : 0.f;
        x = warpSum(x);
        if (lane == 0) sbc = x;
    }
    __syncthreads();
    float mu = sbc * (1.0f / 128.0f);
    float dv = v - mu;

    float s2 = warpSum(dv * dv);
    if (lane == 0) sred[wid] = s2;
    __syncthreads();
    if (wid == 0) {
        float x = (lane < 4) ? sred[lane] : 0.f;
        x = warpSum(x);
        if (lane == 0) sbc = x;
    }
    __syncthreads();
    float var = sbc * (1.0f / 128.0f);
    X[(size_t)n * 128 + d] = dv * rsqrtf(var + 1e-5f) * gw[d] + gb[d];
}

// ---------------- segment mean pool + classifier ----------------
__global__ __launch_bounds__(128) void pool_classify(
    const float* __restrict__ H2, const float* __restrict__ Wc,
    const float* __restrict__ bc, float* __restrict__ out)
{
    int b = blockIdx.x;   // 0..31
    int d = threadIdx.x;  // 0..127

    // lower bounds in sorted g_bh
    int l = 0, r = NHYP;
    while (l < r) { int m = (l + r) >> 1; if (g_bh[m] < b) l = m + 1; else r = m; }
    int s0 = l;
    l = s0; r = NHYP;
    while (l < r) { int m = (l + r) >> 1; if (g_bh[m] < b + 1) l = m + 1; else r = m; }
    int e0 = l;

    float sum = 0.f;
    for (int n = s0; n < e0; n++) sum += H2[(size_t)n * 128 + d];
    float cnt = (float)(e0 - s0);
    float pooled = sum / fmaxf(cnt, 1.0f);

    __shared__ float sp[128];
    sp[d] = pooled;
    __syncthreads();
    if (d < 3) {
        float o = bc[d];
        for (int k = 0; k < 128; k++) o = fmaf(sp[k], Wc[k * 3 + d], o);
        out[b * 3 + d] = o;
    }
}

// ---------------- host launch ----------------
extern "C" void kernel_launch(void* const* d_in, const int* in_sizes, int n_in,
                              void* d_out, int out_size)
{
    const float* ctx_p = (const float*)d_in[0];
    const float* ctx_h = (const float*)d_in[1];
    const float* lhs_p = (const float*)d_in[2];
    const float* lhs_h = (const float*)d_in[3];
    const void*  batch_p = d_in[4];
    const void*  batch_h = d_in[5];
    const float* Wq = (const float*)d_in[6];
    const float* bq = (const float*)d_in[7];
    const float* Wk = (const float*)d_in[8];
    const float* bk = (const float*)d_in[9];
    const float* Wv = (const float*)d_in[10];
    const float* bv = (const float*)d_in[11];
    const float* W1 = (const float*)d_in[12];
    const float* b1 = (const float*)d_in[13];
    const float* W2 = (const float*)d_in[14];
    const float* ln_g = (const float*)d_in[15];
    const float* ln_b = (const float*)d_in[16];
    const float* Wc = (const float*)d_in[17];
    const float* bc = (const float*)d_in[18];
    float* out = (float*)d_out;

    float *Qp, *Kp, *V, *S, *Att, *F, *H1, *H2;
    cudaGetSymbolAddress((void**)&Qp, g_Qp);
    cudaGetSymbolAddress((void**)&Kp, g_Kp);
    cudaGetSymbolAddress((void**)&V, g_V);
    cudaGetSymbolAddress((void**)&S, g_S);
    cudaGetSymbolAddress((void**)&Att, g_att);
    cudaGetSymbolAddress((void**)&F, g_feats);
    cudaGetSymbolAddress((void**)&H1, g_h1);
    cudaGetSymbolAddress((void**)&H2, g_h2);

    conv_batch<<<1, 256>>>(batch_p, batch_h, NPREM);

    // projections
    sgemm_nn<1><<<dim3(DIM / 128, NHYP / 128), 256>>>(ctx_h, Wq, bq, Qp, NHYP, DIM, DIM);
    sgemm_nn<1><<<dim3(DIM / 128, NPREM / 128), 256>>>(ctx_p, Wk, bk, Kp, NPREM, DIM, DIM);
    sgemm_nn<0><<<dim3(BD / 128, NPREM / 128), 256>>>(lhs_p, Wv, bv, V, NPREM, BD, BD);

    // attention
    sgemm_nt_logits<<<dim3(NPREM / 128, NHYP / 128, NHEAD), 256>>>(Qp, Kp, S);
    softmax_mask<<<dim3(NHYP, NHEAD), 256>>>(S);
    sgemm_att<<<dim3(1, NHYP / 128, NHEAD), 512>>>(S, V, Att);

    // mlp
    {
        size_t total = (size_t)NHYP * FEAT;
        int thr = 256;
        int blk = (int)((total + thr - 1) / thr);
        build_feats<<<blk, thr>>>(ctx_h, lhs_h);
    }
    sgemm_nn<2><<<dim3(256 / 128, NHYP / 128), 256>>>(F, W1, b1, H1, NHYP, 256, FEAT);
    sgemm_nn<0><<<dim3(1, NHYP / 128), 256>>>(H1, W2, (const float*)nullptr, H2, NHYP, 128, 256);
    layernorm_inplace<<<NHYP, 128>>>(H2, ln_g, ln_b);

    // pool + classify
    pool_classify<<<NB, 128>>>(H2, Wc, bc, out);

    (void)in_sizes; (void)n_in; (void)out_size;
}

// round 2
// speedup vs baseline: 1.9770x; 1.9770x over previous
#include <cuda_runtime.h>
#include <math.h>
#include <stdint.h>

#define NHYP 4096
#define NPREM 4096
#define DIM 512
#define BD 768
#define NHEAD 4
#define ATND 128
#define NB 32
#define FEAT (DIM + BD)   // 1280

// ---------------- scratch ----------------
__device__ float g_Qp[(size_t)NHEAD * NHYP * ATND];     // [h][n][d]
__device__ float g_Kp[(size_t)NHEAD * NPREM * ATND];    // [h][m][d]
__device__ float g_V[(size_t)NPREM * BD];
__device__ float g_S[(size_t)NHEAD * NHYP * NPREM];     // 256 MB
__device__ float g_att[(size_t)NHYP * BD];
__device__ float g_feats[(size_t)NHYP * FEAT];
__device__ float g_h1[(size_t)NHYP * 256];
__device__ float g_h2[(size_t)NHYP * 128];
__device__ int   g_bp[NPREM];
__device__ int   g_bh[NHYP];

// ---------------- batch id dtype detect + convert ----------------
__global__ void conv_batch(const void* bpr, const void* bhr, int n) {
    __shared__ int s_is64;
    if (threadIdx.x == 0) {
        const int* w = (const int*)bhr;
        int z = 0;
        for (int i = 0; i < 32; i++) {
            int idx = n / 2 + 2 * i + 1;
            if (w[idx] == 0) z++;
        }
        s_is64 = (z > 16) ? 1 : 0;
    }
    __syncthreads();
    int is64 = s_is64;
    const int* bp32 = (const int*)bpr;
    const int* bh32 = (const int*)bhr;
    for (int i = threadIdx.x; i < n; i += blockDim.x) {
        g_bp[i] = is64 ? bp32[2 * i] : bp32[i];
        g_bh[i] = is64 ? bh32[2 * i] : bh32[i];
    }
}

// ---------------- tf32 helpers ----------------
__device__ __forceinline__ uint32_t f2tf32(float f) {
    uint32_t u;
    asm("cvt.rna.tf32.f32 %0, %1;" : "=r"(u) : "f"(f));
    return u;
}

__device__ __forceinline__ void mma_tf32(float c[4], const uint32_t a[4], const uint32_t b[2]) {
    asm volatile(
        "mma.sync.aligned.m16n8k8.row.col.f32.tf32.tf32.f32 "
        "{%0,%1,%2,%3}, {%4,%5,%6,%7}, {%8,%9}, {%0,%1,%2,%3};\n"
        : "+f"(c[0]), "+f"(c[1]), "+f"(c[2]), "+f"(c[3])
        : "r"(a[0]), "r"(a[1]), "r"(a[2]), "r"(a[3]), "r"(b[0]), "r"(b[1]));
}

// ---------------- tf32 tensor-core GEMM ----------------
// CTA tile 128x128, BK=16, 8 warps each 64x32 (warp grid 2x4).
// TB: 0 = B stored [K][N] (NN), 1 = B stored [N][K] (NT, e.g. Q.K^T)
// EPI: 0 plain(+bias if nonnull, col<Nreal guard)
//      1 q/k head-permute store (+bias)
//      2 gelu(+bias)
//      3 scale by 1/sqrt(128)
template <int EPI, int TB>
__global__ __launch_bounds__(256) void mma_gemm(
    const float* __restrict__ A, int lda, size_t sA,
    const float* __restrict__ B, int ldb, size_t sB,
    const float* __restrict__ bias,
    float* __restrict__ C, int ldc, size_t sC,
    int M, int K, int Nreal)
{
    A += (size_t)blockIdx.z * sA;
    B += (size_t)blockIdx.z * sB;
    C += (size_t)blockIdx.z * sC;

    __shared__ uint32_t As[16][140];
    __shared__ uint32_t Bs[16][140];

    int tid = threadIdx.x;
    int i0 = blockIdx.y * 128;
    int j0 = blockIdx.x * 128;
    int w = tid >> 5, lane = tid & 31;
    int g = lane >> 2, tg = lane & 3;
    int wm = (w >> 2) * 64;
    int wn = (w & 3) * 32;

    float acc[4][4][4];
#pragma unroll
    for (int i = 0; i < 4; i++)
#pragma unroll
        for (int j = 0; j < 4; j++)
#pragma unroll
            for (int v = 0; v < 4; v++) acc[i][j][v] = 0.f;

    // A-load mapping (also B when TB==1): 4 threads/row, float4 along K
    int amr = tid >> 2;            // local row 0..63 (+64 for l=1)
    int akc = (tid & 3) * 4;       // k offset 0/4/8/12
    // B NN mapping: float4 along N
    int bkr = tid >> 5;            // k row 0..7 (+8 for l=1)
    int bnc = (tid & 31) * 4;      // n offset 0..124

    float4 a_reg[2], b_reg[2];
    int ntile = K / 16;

    // prefetch tile 0
    {
        int k0 = 0;
#pragma unroll
        for (int l = 0; l < 2; l++) {
            a_reg[l] = *(const float4*)&A[(size_t)(i0 + amr + l * 64) * lda + k0 + akc];
            if (TB == 0) {
                int n = j0 + bnc;
                if (n < Nreal)
                    b_reg[l] = *(const float4*)&B[(size_t)(k0 + bkr + l * 8) * ldb + n];
                else
                    b_reg[l] = make_float4(0.f, 0.f, 0.f, 0.f);
            } else {
                int n = j0 + amr + l * 64;
                if (n < Nreal)
                    b_reg[l] = *(const float4*)&B[(size_t)n * ldb + k0 + akc];
                else
                    b_reg[l] = make_float4(0.f, 0.f, 0.f, 0.f);
            }
        }
    }

    for (int t = 0; t < ntile; t++) {
        // store staged regs -> smem (tf32 converted)
#pragma unroll
        for (int l = 0; l < 2; l++) {
            int m = amr + l * 64;
            As[akc + 0][m] = f2tf32(a_reg[l].x);
            As[akc + 1][m] = f2tf32(a_reg[l].y);
            As[akc + 2][m] = f2tf32(a_reg[l].z);
            As[akc + 3][m] = f2tf32(a_reg[l].w);
            if (TB == 0) {
                uint4 tb;
                tb.x = f2tf32(b_reg[l].x); tb.y = f2tf32(b_reg[l].y);
                tb.z = f2tf32(b_reg[l].z); tb.w = f2tf32(b_reg[l].w);
                *(uint4*)&Bs[bkr + l * 8][bnc] = tb;
            } else {
                int n = amr + l * 64;
                Bs[akc + 0][n] = f2tf32(b_reg[l].x);
                Bs[akc + 1][n] = f2tf32(b_reg[l].y);
                Bs[akc + 2][n] = f2tf32(b_reg[l].z);
                Bs[akc + 3][n] = f2tf32(b_reg[l].w);
            }
        }
        __syncthreads();

        // prefetch next tile
        if (t + 1 < ntile) {
            int k0 = (t + 1) * 16;
#pragma unroll
            for (int l = 0; l < 2; l++) {
                a_reg[l] = *(const float4*)&A[(size_t)(i0 + amr + l * 64) * lda + k0 + akc];
                if (TB == 0) {
                    int n = j0 + bnc;
                    if (n < Nreal)
                        b_reg[l] = *(const float4*)&B[(size_t)(k0 + bkr + l * 8) * ldb + n];
                    else
                        b_reg[l] = make_float4(0.f, 0.f, 0.f, 0.f);
                } else {
                    int n = j0 + amr + l * 64;
                    if (n < Nreal)
                        b_reg[l] = *(const float4*)&B[(size_t)n * ldb + k0 + akc];
                    else
                        b_reg[l] = make_float4(0.f, 0.f, 0.f, 0.f);
                }
            }
        }

        // compute 2 k-steps of 8
#pragma unroll
        for (int ks = 0; ks < 2; ks++) {
            int kk = ks * 8;
            uint32_t af[4][4], bf[4][2];
#pragma unroll
            for (int mt = 0; mt < 4; mt++) {
                int m0 = wm + mt * 16;
                af[mt][0] = As[kk + tg][m0 + g];
                af[mt][1] = As[kk + tg][m0 + g + 8];
                af[mt][2] = As[kk + tg + 4][m0 + g];
                af[mt][3] = As[kk + tg + 4][m0 + g + 8];
            }
#pragma unroll
            for (int nt = 0; nt < 4; nt++) {
                int n0 = wn + nt * 8;
                bf[nt][0] = Bs[kk + tg][n0 + g];
                bf[nt][1] = Bs[kk + tg + 4][n0 + g];
            }
#pragma unroll
            for (int mt = 0; mt < 4; mt++)
#pragma unroll
                for (int nt = 0; nt < 4; nt++)
                    mma_tf32(acc[mt][nt], af[mt], bf[nt]);
        }
        __syncthreads();
    }

    // ---------------- epilogue ----------------
    const float LSCALE = 0.08838834764831845f;  // 1/sqrt(128)
#pragma unroll
    for (int mt = 0; mt < 4; mt++) {
        int r0 = i0 + wm + mt * 16 + g;
#pragma unroll
        for (int nt = 0; nt < 4; nt++) {
            int c0 = j0 + wn + nt * 8 + 2 * tg;
#pragma unroll
            for (int v = 0; v < 4; v++) {
                int r = r0 + (v >> 1) * 8;
                int c = c0 + (v & 1);
                float val = acc[mt][nt][v];
                if (EPI == 1) {
                    val += bias[c];
                    C[(((size_t)(c & 3) * M) + r) * ATND + (c >> 2)] = val;
                } else if (EPI == 3) {
                    C[(size_t)r * ldc + c] = val * LSCALE;
                } else {
                    if (c < Nreal) {
                        if (bias) val += bias[c];
                        if (EPI == 2)
                            val = 0.5f * val * (1.0f + erff(val * 0.70710678118654752f));
                        C[(size_t)r * ldc + c] = val;
                    }
                }
            }
        }
    }
}

// ---------------- warp reductions ----------------
__device__ __forceinline__ float warpMax(float v) {
#pragma unroll
    for (int o = 16; o; o >>= 1) v = fmaxf(v, __shfl_xor_sync(0xffffffffu, v, o));
    return v;
}
__device__ __forceinline__ float warpSum(float v) {
#pragma unroll
    for (int o = 16; o; o >>= 1) v += __shfl_xor_sync(0xffffffffu, v, o);
    return v;
}

// ---------------- masked softmax over m, in place ----------------
__global__ __launch_bounds__(256) void softmax_mask(float* __restrict__ S)
{
    int n = blockIdx.x;
    int h = blockIdx.y;
    float* row = S + ((size_t)h * NHYP + n) * NPREM;
    int tid = threadIdx.x;
    int myb = g_bh[n];

    float v[16];
    float mx = -INFINITY;
#pragma unroll
    for (int t = 0; t < 16; t++) {
        int m = t * 256 + tid;
        float x = row[m];
        if (g_bp[m] == myb) x = -1e10f;
        v[t] = x;
        mx = fmaxf(mx, x);
    }
    __shared__ float sred[8];
    __shared__ float sbc;
    float wm = warpMax(mx);
    int lane = tid & 31, wid = tid >> 5;
    if (lane == 0) sred[wid] = wm;
    __syncthreads();
    if (wid == 0) {
        float x = (lane < 8) ? sred[lane] : -INFINITY;
        x = warpMax(x);
        if (lane == 0) sbc = x;
    }
    __syncthreads();
    mx = sbc;

    float s = 0.f;
#pragma unroll
    for (int t = 0; t < 16; t++) {
        float e = expf(v[t] - mx);
        v[t] = e;
        s += e;
    }
    float ws = warpSum(s);
    if (lane == 0) sred[wid] = ws;
    __syncthreads();
    if (wid == 0) {
        float x = (lane < 8) ? sred[lane] : 0.f;
        x = warpSum(x);
        if (lane == 0) sbc = x;
    }
    __syncthreads();
    float inv = 1.0f / sbc;
#pragma unroll
    for (int t = 0; t < 16; t++) row[t * 256 + tid] = v[t] * inv;
}

// ---------------- feats = concat(ctx_h, lhs_h - attended) ----------------
__global__ void build_feats(const float* __restrict__ ctx_h, const float* __restrict__ lhs_h)
{
    size_t idx = (size_t)blockIdx.x * blockDim.x + threadIdx.x;
    if (idx >= (size_t)NHYP * FEAT) return;
    int n = (int)(idx / FEAT);
    int j = (int)(idx % FEAT);
    float v;
    if (j < DIM) v = ctx_h[(size_t)n * DIM + j];
    else {
        int jj = j - DIM;
        v = lhs_h[(size_t)n * BD + jj] - g_att[(size_t)n * BD + jj];
    }
    g_feats[idx] = v;
}

// ---------------- layernorm(128) in place ----------------
__global__ __launch_bounds__(128) void layernorm_inplace(
    float* __restrict__ X, const float* __restrict__ gw, const float* __restrict__ gb)
{
    int n = blockIdx.x;
    int d = threadIdx.x;
    float v = X[(size_t)n * 128 + d];
    __shared__ float sred[4];
    __shared__ float sbc;
    int lane = d & 31, wid = d >> 5;

    float s = warpSum(v);
    if (lane == 0) sred[wid] = s;
    __syncthreads();
    if (wid == 0) {
        float x = (lane < 4) ? sred[lane] : 0.f;
        x = warpSum(x);
        if (lane == 0) sbc = x;
    }
    __syncthreads();
    float mu = sbc * (1.0f / 128.0f);
    float dv = v - mu;

    float s2 = warpSum(dv * dv);
    if (lane == 0) sred[wid] = s2;
    __syncthreads();
    if (wid == 0) {
        float x = (lane < 4) ? sred[lane] : 0.f;
        x = warpSum(x);
        if (lane == 0) sbc = x;
    }
    __syncthreads();
    float var = sbc * (1.0f / 128.0f);
    X[(size_t)n * 128 + d] = dv * rsqrtf(var + 1e-5f) * gw[d] + gb[d];
}

// ---------------- segment mean pool + classifier ----------------
__global__ __launch_bounds__(128) void pool_classify(
    const float* __restrict__ H2, const float* __restrict__ Wc,
    const float* __restrict__ bc, float* __restrict__ out)
{
    int b = blockIdx.x;
    int d = threadIdx.x;

    int l = 0, r = NHYP;
    while (l < r) { int m = (l + r) >> 1; if (g_bh[m] < b) l = m + 1; else r = m; }
    int s0 = l;
    l = s0; r = NHYP;
    while (l < r) { int m = (l + r) >> 1; if (g_bh[m] < b + 1) l = m + 1; else r = m; }
    int e0 = l;

    float sum = 0.f;
    for (int n = s0; n < e0; n++) sum += H2[(size_t)n * 128 + d];
    float cnt = (float)(e0 - s0);
    float pooled = sum / fmaxf(cnt, 1.0f);

    __shared__ float sp[128];
    sp[d] = pooled;
    __syncthreads();
    if (d < 3) {
        float o = bc[d];
        for (int k = 0; k < 128; k++) o = fmaf(sp[k], Wc[k * 3 + d], o);
        out[b * 3 + d] = o;
    }
}

// ---------------- host launch ----------------
extern "C" void kernel_launch(void* const* d_in, const int* in_sizes, int n_in,
                              void* d_out, int out_size)
{
    const float* ctx_p = (const float*)d_in[0];
    const float* ctx_h = (const float*)d_in[1];
    const float* lhs_p = (const float*)d_in[2];
    const float* lhs_h = (const float*)d_in[3];
    const void*  batch_p = d_in[4];
    const void*  batch_h = d_in[5];
    const float* Wq = (const float*)d_in[6];
    const float* bq = (const float*)d_in[7];
    const float* Wk = (const float*)d_in[8];
    const float* bk = (const float*)d_in[9];
    const float* Wv = (const float*)d_in[10];
    const float* bv = (const float*)d_in[11];
    const float* W1 = (const float*)d_in[12];
    const float* b1 = (const float*)d_in[13];
    const float* W2 = (const float*)d_in[14];
    const float* ln_g = (const float*)d_in[15];
    const float* ln_b = (const float*)d_in[16];
    const float* Wc = (const float*)d_in[17];
    const float* bc = (const float*)d_in[18];
    float* out = (float*)d_out;

    float *Qp, *Kp, *V, *S, *Att, *F, *H1, *H2;
    cudaGetSymbolAddress((void**)&Qp, g_Qp);
    cudaGetSymbolAddress((void**)&Kp, g_Kp);
    cudaGetSymbolAddress((void**)&V, g_V);
    cudaGetSymbolAddress((void**)&S, g_S);
    cudaGetSymbolAddress((void**)&Att, g_att);
    cudaGetSymbolAddress((void**)&F, g_feats);
    cudaGetSymbolAddress((void**)&H1, g_h1);
    cudaGetSymbolAddress((void**)&H2, g_h2);

    conv_batch<<<1, 256>>>(batch_p, batch_h, NPREM);

    // projections (tensor core tf32)
    mma_gemm<1, 0><<<dim3(4, 32), 256>>>(ctx_h, DIM, 0, Wq, DIM, 0, bq,
                                         Qp, 0, 0, NHYP, DIM, DIM);
    mma_gemm<1, 0><<<dim3(4, 32), 256>>>(ctx_p, DIM, 0, Wk, DIM, 0, bk,
                                         Kp, 0, 0, NPREM, DIM, DIM);
    mma_gemm<0, 0><<<dim3(6, 32), 256>>>(lhs_p, BD, 0, Wv, BD, 0, bv,
                                         V, BD, 0, NPREM, BD, BD);

    // attention logits: S[h] = scale * Qp[h] @ Kp[h]^T
    mma_gemm<3, 1><<<dim3(32, 32, NHEAD), 256>>>(
        Qp, ATND, (size_t)NHYP * ATND,
        Kp, ATND, (size_t)NPREM * ATND,
        (const float*)nullptr,
        S, NPREM, (size_t)NHYP * NPREM,
        NHYP, ATND, NPREM);

    softmax_mask<<<dim3(NHYP, NHEAD), 256>>>(S);

    // attended[h] = P[h] @ V[:, h*192 : (h+1)*192]   (N padded 192->256)
    mma_gemm<0, 0><<<dim3(2, 32, NHEAD), 256>>>(
        S, NPREM, (size_t)NHYP * NPREM,
        V, BD, 192,
        (const float*)nullptr,
        Att, BD, 192,
        NHYP, NPREM, 192);

    // mlp
    {
        size_t total = (size_t)NHYP * FEAT;
        int thr = 256;
        int blk = (int)((total + thr - 1) / thr);
        build_feats<<<blk, thr>>>(ctx_h, lhs_h);
    }
    mma_gemm<2, 0><<<dim3(2, 32), 256>>>(F, FEAT, 0, W1, 256, 0, b1,
                                         H1, 256, 0, NHYP, FEAT, 256);
    mma_gemm<0, 0><<<dim3(1, 32), 256>>>(H1, 256, 0, W2, 128, 0,
                                         (const float*)nullptr,
                                         H2, 128, 0, NHYP, 256, 128);
    layernorm_inplace<<<NHYP, 128>>>(H2, ln_g, ln_b);

    pool_classify<<<NB, 128>>>(H2, Wc, bc, out);

    (void)in_sizes; (void)n_in; (void)out_size;
}

// round 3
// speedup vs baseline: 3.2162x; 1.6269x over previous
#include <cuda_runtime.h>
#include <math.h>
#include <stdint.h>

#define NHYP 4096
#define NPREM 4096
#define DIM 512
#define BD 768
#define NHEAD 4
#define ATND 128
#define NB 32
#define FEAT (DIM + BD)   // 1280

// ---------------- scratch ----------------
__device__ float g_Qp[(size_t)NHEAD * NHYP * ATND];     // [h][n][d] tf32 bits
__device__ float g_Kp[(size_t)NHEAD * NPREM * ATND];    // [h][m][d] tf32 bits
__device__ float g_V[(size_t)NPREM * BD];               // tf32 bits
__device__ float g_att[(size_t)NHYP * BD];
__device__ float g_feats[(size_t)NHYP * FEAT];
__device__ float g_h1[(size_t)NHYP * 256];
__device__ float g_h2[(size_t)NHYP * 128];
__device__ int   g_bp[NPREM];
__device__ int   g_bh[NHYP];

// ---------------- batch id dtype detect + convert ----------------
__global__ void conv_batch(const void* bpr, const void* bhr, int n) {
    __shared__ int s_is64;
    if (threadIdx.x == 0) {
        const int* w = (const int*)bhr;
        int z = 0;
        for (int i = 0; i < 32; i++) {
            int idx = n / 2 + 2 * i + 1;
            if (w[idx] == 0) z++;
        }
        s_is64 = (z > 16) ? 1 : 0;
    }
    __syncthreads();
    int is64 = s_is64;
    const int* bp32 = (const int*)bpr;
    const int* bh32 = (const int*)bhr;
    for (int i = threadIdx.x; i < n; i += blockDim.x) {
        g_bp[i] = is64 ? bp32[2 * i] : bp32[i];
        g_bh[i] = is64 ? bh32[2 * i] : bh32[i];
    }
}

// ---------------- tf32 helpers ----------------
__device__ __forceinline__ uint32_t f2tf32(float f) {
    uint32_t u;
    asm("cvt.rna.tf32.f32 %0, %1;" : "=r"(u) : "f"(f));
    return u;
}

__device__ __forceinline__ void mma_tf32(float c[4], const uint32_t a[4], const uint32_t b[2]) {
    asm volatile(
        "mma.sync.aligned.m16n8k8.row.col.f32.tf32.tf32.f32 "
        "{%0,%1,%2,%3}, {%4,%5,%6,%7}, {%8,%9}, {%0,%1,%2,%3};\n"
        : "+f"(c[0]), "+f"(c[1]), "+f"(c[2]), "+f"(c[3])
        : "r"(a[0]), "r"(a[1]), "r"(a[2]), "r"(a[3]), "r"(b[0]), "r"(b[1]));
}

__device__ __forceinline__ void cp16(uint32_t saddr, const void* gaddr) {
    asm volatile("cp.async.cg.shared.global [%0], [%1], 16;"
                 :: "r"(saddr), "l"(gaddr) : "memory");
}

// ---------------- tf32 tensor-core GEMM ----------------
// CTA tile 128x128, BK=16, 8 warps each 64x32.
// EPI: 0 plain(+bias, col guard); 1 q/k head-permute store as tf32 bits (+bias);
//      2 gelu(+bias); 4 plain store as tf32 bits (+bias, col guard)
template <int EPI, int TB>
__global__ __launch_bounds__(256) void mma_gemm(
    const float* __restrict__ A, int lda, size_t sA,
    const float* __restrict__ B, int ldb, size_t sB,
    const float* __restrict__ bias,
    float* __restrict__ C, int ldc, size_t sC,
    int M, int K, int Nreal)
{
    A += (size_t)blockIdx.z * sA;
    B += (size_t)blockIdx.z * sB;
    C += (size_t)blockIdx.z * sC;

    __shared__ uint32_t As[16][140];
    __shared__ uint32_t Bs[16][140];

    int tid = threadIdx.x;
    int i0 = blockIdx.y * 128;
    int j0 = blockIdx.x * 128;
    int w = tid >> 5, lane = tid & 31;
    int g = lane >> 2, tg = lane & 3;
    int wm = (w >> 2) * 64;
    int wn = (w & 3) * 32;

    float acc[4][4][4];
#pragma unroll
    for (int i = 0; i < 4; i++)
#pragma unroll
        for (int j = 0; j < 4; j++)
#pragma unroll
            for (int v = 0; v < 4; v++) acc[i][j][v] = 0.f;

    int amr = tid >> 2;
    int akc = (tid & 3) * 4;
    int bkr = tid >> 5;
    int bnc = (tid & 31) * 4;

    float4 a_reg[2], b_reg[2];
    int ntile = K / 16;

    {
        int k0 = 0;
#pragma unroll
        for (int l = 0; l < 2; l++) {
            a_reg[l] = *(const float4*)&A[(size_t)(i0 + amr + l * 64) * lda + k0 + akc];
            if (TB == 0) {
                int n = j0 + bnc;
                if (n < Nreal)
                    b_reg[l] = *(const float4*)&B[(size_t)(k0 + bkr + l * 8) * ldb + n];
                else
                    b_reg[l] = make_float4(0.f, 0.f, 0.f, 0.f);
            } else {
                int n = j0 + amr + l * 64;
                if (n < Nreal)
                    b_reg[l] = *(const float4*)&B[(size_t)n * ldb + k0 + akc];
                else
                    b_reg[l] = make_float4(0.f, 0.f, 0.f, 0.f);
            }
        }
    }

    for (int t = 0; t < ntile; t++) {
#pragma unroll
        for (int l = 0; l < 2; l++) {
            int m = amr + l * 64;
            As[akc + 0][m] = f2tf32(a_reg[l].x);
            As[akc + 1][m] = f2tf32(a_reg[l].y);
            As[akc + 2][m] = f2tf32(a_reg[l].z);
            As[akc + 3][m] = f2tf32(a_reg[l].w);
            if (TB == 0) {
                uint4 tb;
                tb.x = f2tf32(b_reg[l].x); tb.y = f2tf32(b_reg[l].y);
                tb.z = f2tf32(b_reg[l].z); tb.w = f2tf32(b_reg[l].w);
                *(uint4*)&Bs[bkr + l * 8][bnc] = tb;
            } else {
                int n = amr + l * 64;
                Bs[akc + 0][n] = f2tf32(b_reg[l].x);
                Bs[akc + 1][n] = f2tf32(b_reg[l].y);
                Bs[akc + 2][n] = f2tf32(b_reg[l].z);
                Bs[akc + 3][n] = f2tf32(b_reg[l].w);
            }
        }
        __syncthreads();

        if (t + 1 < ntile) {
            int k0 = (t + 1) * 16;
#pragma unroll
            for (int l = 0; l < 2; l++) {
                a_reg[l] = *(const float4*)&A[(size_t)(i0 + amr + l * 64) * lda + k0 + akc];
                if (TB == 0) {
                    int n = j0 + bnc;
                    if (n < Nreal)
                        b_reg[l] = *(const float4*)&B[(size_t)(k0 + bkr + l * 8) * ldb + n];
                    else
                        b_reg[l] = make_float4(0.f, 0.f, 0.f, 0.f);
                } else {
                    int n = j0 + amr + l * 64;
                    if (n < Nreal)
                        b_reg[l] = *(const float4*)&B[(size_t)n * ldb + k0 + akc];
                    else
                        b_reg[l] = make_float4(0.f, 0.f, 0.f, 0.f);
                }
            }
        }

#pragma unroll
        for (int ks = 0; ks < 2; ks++) {
            int kk = ks * 8;
            uint32_t af[4][4], bf[4][2];
#pragma unroll
            for (int mt = 0; mt < 4; mt++) {
                int m0 = wm + mt * 16;
                af[mt][0] = As[kk + tg][m0 + g];
                af[mt][1] = As[kk + tg][m0 + g + 8];
                af[mt][2] = As[kk + tg + 4][m0 + g];
                af[mt][3] = As[kk + tg + 4][m0 + g + 8];
            }
#pragma unroll
            for (int nt = 0; nt < 4; nt++) {
                int n0 = wn + nt * 8;
                bf[nt][0] = Bs[kk + tg][n0 + g];
                bf[nt][1] = Bs[kk + tg + 4][n0 + g];
            }
#pragma unroll
            for (int mt = 0; mt < 4; mt++)
#pragma unroll
                for (int nt = 0; nt < 4; nt++)
                    mma_tf32(acc[mt][nt], af[mt], bf[nt]);
        }
        __syncthreads();
    }

#pragma unroll
    for (int mt = 0; mt < 4; mt++) {
        int r0 = i0 + wm + mt * 16 + g;
#pragma unroll
        for (int nt = 0; nt < 4; nt++) {
            int c0 = j0 + wn + nt * 8 + 2 * tg;
#pragma unroll
            for (int v = 0; v < 4; v++) {
                int r = r0 + (v >> 1) * 8;
                int c = c0 + (v & 1);
                float val = acc[mt][nt][v];
                if (EPI == 1) {
                    val += bias[c];
                    *(uint32_t*)&C[(((size_t)(c & 3) * M) + r) * ATND + (c >> 2)] = f2tf32(val);
                } else if (EPI == 4) {
                    if (c < Nreal) {
                        val += bias[c];
                        *(uint32_t*)&C[(size_t)r * ldc + c] = f2tf32(val);
                    }
                } else {
                    if (c < Nreal) {
                        if (bias) val += bias[c];
                        if (EPI == 2)
                            val = 0.5f * val * (1.0f + erff(val * 0.70710678118654752f));
                        C[(size_t)r * ldc + c] = val;
                    }
                }
            }
        }
    }
}

// ---------------- fused flash attention ----------------
// grid (NHYP/128, NHEAD), 256 threads (8 warps x 16 q-rows).
// smem words: Qs[128*132] @0 | Ks[2][32*132] @16896 | Vs[2][32*200] @25344 | bp[2][32] @38144
#define FA_SMEM_BYTES ((38144 + 64) * 4)

__global__ __launch_bounds__(256, 1) void flash_attn()
{
    extern __shared__ uint32_t su[];
    const int tid = threadIdx.x;
    const int w = tid >> 5, lane = tid & 31;
    const int g = lane >> 2, tg = lane & 3;
    const int i0 = blockIdx.x * 128;
    const int h  = blockIdx.y;
    const int wm = w * 16;

    const uint32_t* gQ  = (const uint32_t*)g_Qp + ((size_t)h * NHYP + i0) * ATND;
    const uint32_t* gK0 = (const uint32_t*)g_Kp + (size_t)h * NPREM * ATND;
    const uint32_t* gV0 = (const uint32_t*)g_V + h * 192;

    uint32_t sbase = (uint32_t)__cvta_generic_to_shared(su);
    int* sbp = (int*)(su + 38144);

    // Q tile 128x128 (tf32 bits), stride 132
#pragma unroll
    for (int i = 0; i < 16; i++) {
        int flat = i * 256 + tid;
        int row = flat >> 5, ch = (flat & 31) * 4;
        *(uint4*)&su[row * 132 + ch] = *(const uint4*)&gQ[row * 128 + ch];
    }

    // prefetch premise tile 0
    {
        int ch = (tid & 31) * 4;
#pragma unroll
        for (int r = 0; r < 4; r++) {
            int row = r * 8 + w;
            cp16(sbase + (16896 + row * 132 + ch) * 4, gK0 + (size_t)row * 128 + ch);
        }
#pragma unroll
        for (int i = 0; i < 6; i++) {
            int flat = i * 256 + tid;
            int row = flat / 48, vc = (flat % 48) * 4;
            cp16(sbase + (25344 + row * 200 + vc) * 4, gV0 + (size_t)row * 768 + vc);
        }
        if (tid < 32) sbp[tid] = g_bp[tid];
        asm volatile("cp.async.commit_group;" ::: "memory");
    }

    const int brow0 = g_bh[i0 + wm + g];
    const int brow1 = g_bh[i0 + wm + g + 8];

    float o[24][4];
#pragma unroll
    for (int nt = 0; nt < 24; nt++) { o[nt][0] = o[nt][1] = o[nt][2] = o[nt][3] = 0.f; }
    float mr0 = -INFINITY, mr1 = -INFINITY, lr0 = 0.f, lr1 = 0.f;

    const int NT = NPREM / 32;
    for (int t = 0; t < NT; t++) {
        int buf = t & 1;
        if (t + 1 < NT) {
            int nbuf = buf ^ 1;
            int m0n = (t + 1) * 32;
            const uint32_t* gK = gK0 + (size_t)m0n * 128;
            int ch = (tid & 31) * 4;
#pragma unroll
            for (int r = 0; r < 4; r++) {
                int row = r * 8 + w;
                cp16(sbase + (16896 + nbuf * 4224 + row * 132 + ch) * 4,
                     gK + (size_t)row * 128 + ch);
            }
#pragma unroll
            for (int i = 0; i < 6; i++) {
                int flat = i * 256 + tid;
                int row = flat / 48, vc = (flat % 48) * 4;
                cp16(sbase + (25344 + nbuf * 6400 + row * 200 + vc) * 4,
                     gV0 + (size_t)(m0n + row) * 768 + vc);
            }
            if (tid < 32) sbp[nbuf * 32 + tid] = g_bp[m0n + tid];
            asm volatile("cp.async.commit_group;" ::: "memory");
            asm volatile("cp.async.wait_group 1;" ::: "memory");
        } else {
            asm volatile("cp.async.wait_group 0;" ::: "memory");
        }
        __syncthreads();

        const uint32_t* Kb = su + 16896 + buf * 4224;
        const uint32_t* Vb = su + 25344 + buf * 6400;
        const int* bpb = sbp + buf * 32;

        // S = Q K^T for 128 q-rows x 32 premise cols
        float sv[4][4];
#pragma unroll
        for (int nt = 0; nt < 4; nt++) sv[nt][0] = sv[nt][1] = sv[nt][2] = sv[nt][3] = 0.f;
#pragma unroll
        for (int ks = 0; ks < 16; ks++) {
            int kk = ks * 8;
            uint32_t a[4];
            a[0] = su[(wm + g) * 132 + kk + tg];
            a[1] = su[(wm + g + 8) * 132 + kk + tg];
            a[2] = su[(wm + g) * 132 + kk + tg + 4];
            a[3] = su[(wm + g + 8) * 132 + kk + tg + 4];
#pragma unroll
            for (int nt = 0; nt < 4; nt++) {
                uint32_t b[2];
                b[0] = Kb[(nt * 8 + g) * 132 + kk + tg];
                b[1] = Kb[(nt * 8 + g) * 132 + kk + tg + 4];
                mma_tf32(sv[nt], a, b);
            }
        }

        // scale + mask + row max
        const float SC = 0.08838834764831845f;
        float tm0 = -INFINITY, tm1 = -INFINITY;
#pragma unroll
        for (int nt = 0; nt < 4; nt++) {
            int c0 = nt * 8 + 2 * tg;
            int b0 = bpb[c0], b1 = bpb[c0 + 1];
            sv[nt][0] = (b0 == brow0) ? -1e10f : sv[nt][0] * SC;
            sv[nt][1] = (b1 == brow0) ? -1e10f : sv[nt][1] * SC;
            sv[nt][2] = (b0 == brow1) ? -1e10f : sv[nt][2] * SC;
            sv[nt][3] = (b1 == brow1) ? -1e10f : sv[nt][3] * SC;
            tm0 = fmaxf(tm0, fmaxf(sv[nt][0], sv[nt][1]));
            tm1 = fmaxf(tm1, fmaxf(sv[nt][2], sv[nt][3]));
        }
        tm0 = fmaxf(tm0, __shfl_xor_sync(0xffffffffu, tm0, 1));
        tm0 = fmaxf(tm0, __shfl_xor_sync(0xffffffffu, tm0, 2));
        tm1 = fmaxf(tm1, __shfl_xor_sync(0xffffffffu, tm1, 1));
        tm1 = fmaxf(tm1, __shfl_xor_sync(0xffffffffu, tm1, 2));

        float mn0 = fmaxf(mr0, tm0), mn1 = fmaxf(mr1, tm1);
        float al0 = __expf(mr0 - mn0), al1 = __expf(mr1 - mn1);
        mr0 = mn0; mr1 = mn1;

        float ts0 = 0.f, ts1 = 0.f;
#pragma unroll
        for (int nt = 0; nt < 4; nt++) {
            sv[nt][0] = __expf(sv[nt][0] - mn0);
            sv[nt][1] = __expf(sv[nt][1] - mn0);
            sv[nt][2] = __expf(sv[nt][2] - mn1);
            sv[nt][3] = __expf(sv[nt][3] - mn1);
            ts0 += sv[nt][0] + sv[nt][1];
            ts1 += sv[nt][2] + sv[nt][3];
        }
        ts0 += __shfl_xor_sync(0xffffffffu, ts0, 1);
        ts0 += __shfl_xor_sync(0xffffffffu, ts0, 2);
        ts1 += __shfl_xor_sync(0xffffffffu, ts1, 1);
        ts1 += __shfl_xor_sync(0xffffffffu, ts1, 2);
        lr0 = lr0 * al0 + ts0;
        lr1 = lr1 * al1 + ts1;

        if (!__all_sync(0xffffffffu, (al0 == 1.f) && (al1 == 1.f))) {
#pragma unroll
            for (int nt = 0; nt < 24; nt++) {
                o[nt][0] *= al0; o[nt][1] *= al0;
                o[nt][2] *= al1; o[nt][3] *= al1;
            }
        }

        // O += P @ V : transpose P C-frags -> A-frags via shuffles
#pragma unroll
        for (int kt = 0; kt < 4; kt++) {
            uint32_t c0 = f2tf32(sv[kt][0]), c1 = f2tf32(sv[kt][1]);
            uint32_t c2 = f2tf32(sv[kt][2]), c3 = f2tf32(sv[kt][3]);
            int srcA = 4 * g + (tg >> 1);
            int srcB = srcA + 2;
            uint32_t t0 = __shfl_sync(0xffffffffu, c0, srcA);
            uint32_t t1 = __shfl_sync(0xffffffffu, c1, srcA);
            uint32_t t2 = __shfl_sync(0xffffffffu, c0, srcB);
            uint32_t t3 = __shfl_sync(0xffffffffu, c1, srcB);
            uint32_t t4 = __shfl_sync(0xffffffffu, c2, srcA);
            uint32_t t5 = __shfl_sync(0xffffffffu, c3, srcA);
            uint32_t t6 = __shfl_sync(0xffffffffu, c2, srcB);
            uint32_t t7 = __shfl_sync(0xffffffffu, c3, srcB);
            bool odd = tg & 1;
            uint32_t a[4];
            a[0] = odd ? t1 : t0;   // P[g][tg]
            a[1] = odd ? t5 : t4;   // P[g+8][tg]
            a[2] = odd ? t3 : t2;   // P[g][tg+4]
            a[3] = odd ? t7 : t6;   // P[g+8][tg+4]
#pragma unroll
            for (int nt = 0; nt < 24; nt++) {
                uint32_t b[2];
                b[0] = Vb[(kt * 8 + tg) * 200 + nt * 8 + g];
                b[1] = Vb[(kt * 8 + tg + 4) * 200 + nt * 8 + g];
                mma_tf32(o[nt], a, b);
            }
        }
        __syncthreads();
    }

    float inv0 = 1.f / lr0, inv1 = 1.f / lr1;
    int r0 = i0 + wm + g, r1 = r0 + 8;
#pragma unroll
    for (int nt = 0; nt < 24; nt++) {
        int c = h * 192 + nt * 8 + 2 * tg;
        *(float2*)&g_att[(size_t)r0 * BD + c] = make_float2(o[nt][0] * inv0, o[nt][1] * inv0);
        *(float2*)&g_att[(size_t)r1 * BD + c] = make_float2(o[nt][2] * inv1, o[nt][3] * inv1);
    }
}

// ---------------- warp reductions ----------------
__device__ __forceinline__ float warpSum(float v) {
#pragma unroll
    for (int of = 16; of; of >>= 1) v += __shfl_xor_sync(0xffffffffu, v, of);
    return v;
}

// ---------------- feats = concat(ctx_h, lhs_h - attended) ----------------
__global__ void build_feats(const float* __restrict__ ctx_h, const float* __restrict__ lhs_h)
{
    size_t idx = (size_t)blockIdx.x * blockDim.x + threadIdx.x;
    if (idx >= (size_t)NHYP * FEAT) return;
    int n = (int)(idx / FEAT);
    int j = (int)(idx % FEAT);
    float v;
    if (j < DIM) v = ctx_h[(size_t)n * DIM + j];
    else {
        int jj = j - DIM;
        v = lhs_h[(size_t)n * BD + jj] - g_att[(size_t)n * BD + jj];
    }
    g_feats[idx] = v;
}

// ---------------- layernorm(128) in place ----------------
__global__ __launch_bounds__(128) void layernorm_inplace(
    float* __restrict__ X, const float* __restrict__ gw, const float* __restrict__ gb)
{
    int n = blockIdx.x;
    int d = threadIdx.x;
    float v = X[(size_t)n * 128 + d];
    __shared__ float sred[4];
    __shared__ float sbc;
    int lane = d & 31, wid = d >> 5;

    float s = warpSum(v);
    if (lane == 0) sred[wid] = s;
    __syncthreads();
    if (wid == 0) {
        float x = (lane < 4) ? sred[lane] : 0.f;
        x = warpSum(x);
        if (lane == 0) sbc = x;
    }
    __syncthreads();
    float mu = sbc * (1.0f / 128.0f);
    float dv = v - mu;

    float s2 = warpSum(dv * dv);
    if (lane == 0) sred[wid] = s2;
    __syncthreads();
    if (wid == 0) {
        float x = (lane < 4) ? sred[lane] : 0.f;
        x = warpSum(x);
        if (lane == 0) sbc = x;
    }
    __syncthreads();
    float var = sbc * (1.0f / 128.0f);
    X[(size_t)n * 128 + d] = dv * rsqrtf(var + 1e-5f) * gw[d] + gb[d];
}

// ---------------- segment mean pool + classifier ----------------
__global__ __launch_bounds__(128) void pool_classify(
    const float* __restrict__ H2, const float* __restrict__ Wc,
    const float* __restrict__ bc, float* __restrict__ out)
{
    int b = blockIdx.x;
    int d = threadIdx.x;

    int l = 0, r = NHYP;
    while (l < r) { int m = (l + r) >> 1; if (g_bh[m] < b) l = m + 1; else r = m; }
    int s0 = l;
    l = s0; r = NHYP;
    while (l < r) { int m = (l + r) >> 1; if (g_bh[m] < b + 1) l = m + 1; else r = m; }
    int e0 = l;

    float sum = 0.f;
    for (int n = s0; n < e0; n++) sum += H2[(size_t)n * 128 + d];
    float cnt = (float)(e0 - s0);
    float pooled = sum / fmaxf(cnt, 1.0f);

    __shared__ float sp[128];
    sp[d] = pooled;
    __syncthreads();
    if (d < 3) {
        float o = bc[d];
        for (int k = 0; k < 128; k++) o = fmaf(sp[k], Wc[k * 3 + d], o);
        out[b * 3 + d] = o;
    }
}

// ---------------- host launch ----------------
extern "C" void kernel_launch(void* const* d_in, const int* in_sizes, int n_in,
                              void* d_out, int out_size)
{
    const float* ctx_p = (const float*)d_in[0];
    const float* ctx_h = (const float*)d_in[1];
    const float* lhs_p = (const float*)d_in[2];
    const float* lhs_h = (const float*)d_in[3];
    const void*  batch_p = d_in[4];
    const void*  batch_h = d_in[5];
    const float* Wq = (const float*)d_in[6];
    const float* bq = (const float*)d_in[7];
    const float* Wk = (const float*)d_in[8];
    const float* bk = (const float*)d_in[9];
    const float* Wv = (const float*)d_in[10];
    const float* bv = (const float*)d_in[11];
    const float* W1 = (const float*)d_in[12];
    const float* b1 = (const float*)d_in[13];
    const float* W2 = (const float*)d_in[14];
    const float* ln_g = (const float*)d_in[15];
    const float* ln_b = (const float*)d_in[16];
    const float* Wc = (const float*)d_in[17];
    const float* bc = (const float*)d_in[18];
    float* out = (float*)d_out;

    float *Qp, *Kp, *V, *F, *H1, *H2;
    cudaGetSymbolAddress((void**)&Qp, g_Qp);
    cudaGetSymbolAddress((void**)&Kp, g_Kp);
    cudaGetSymbolAddress((void**)&V, g_V);
    cudaGetSymbolAddress((void**)&F, g_feats);
    cudaGetSymbolAddress((void**)&H1, g_h1);
    cudaGetSymbolAddress((void**)&H2, g_h2);

    static int fa_attr_done = 0;
    if (!fa_attr_done) {
        cudaFuncSetAttribute(flash_attn, cudaFuncAttributeMaxDynamicSharedMemorySize,
                             FA_SMEM_BYTES);
        fa_attr_done = 1;
    }

    conv_batch<<<1, 256>>>(batch_p, batch_h, NPREM);

    // projections (store tf32 bits)
    mma_gemm<1, 0><<<dim3(4, 32), 256>>>(ctx_h, DIM, 0, Wq, DIM, 0, bq,
                                         Qp, 0, 0, NHYP, DIM, DIM);
    mma_gemm<1, 0><<<dim3(4, 32), 256>>>(ctx_p, DIM, 0, Wk, DIM, 0, bk,
                                         Kp, 0, 0, NPREM, DIM, DIM);
    mma_gemm<4, 0><<<dim3(6, 32), 256>>>(lhs_p, BD, 0, Wv, BD, 0, bv,
                                         V, BD, 0, NPREM, BD, BD);

    // fused attention
    flash_attn<<<dim3(NHYP / 128, NHEAD), 256, FA_SMEM_BYTES>>>();

    // mlp
    {
        size_t total = (size_t)NHYP * FEAT;
        int thr = 256;
        int blk = (int)((total + thr - 1) / thr);
        build_feats<<<blk, thr>>>(ctx_h, lhs_h);
    }
    mma_gemm<2, 0><<<dim3(2, 32), 256>>>(F, FEAT, 0, W1, 256, 0, b1,
                                         H1, 256, 0, NHYP, FEAT, 256);
    mma_gemm<0, 0><<<dim3(1, 32), 256>>>(H1, 256, 0, W2, 128, 0,
                                         (const float*)nullptr,
                                         H2, 128, 0, NHYP, 256, 128);
    layernorm_inplace<<<NHYP, 128>>>(H2, ln_g, ln_b);

    pool_classify<<<NB, 128>>>(H2, Wc, bc, out);

    (void)in_sizes; (void)n_in; (void)out_size;
}

// round 4
// speedup vs baseline: 3.2253x; 1.0028x over previous
#include <cuda_runtime.h>
#include <math.h>
#include <stdint.h>

#define NHYP 4096
#define NPREM 4096
#define DIM 512
#define BD 768
#define NHEAD 4
#define ATND 128
#define NB 32
#define FEAT (DIM + BD)   // 1280

// ---------------- scratch ----------------
__device__ float g_Qp[(size_t)NHEAD * NHYP * ATND];     // [h][n][d] tf32 bits
__device__ float g_Kp[(size_t)NHEAD * NPREM * ATND];    // [h][m][d] tf32 bits
__device__ float g_V[(size_t)NPREM * BD];               // tf32 bits
__device__ float g_att[(size_t)NHYP * BD];
__device__ float g_feats[(size_t)NHYP * FEAT];
__device__ float g_h1[(size_t)NHYP * 256];
__device__ float g_h2[(size_t)NHYP * 128];
__device__ int   g_bp[NPREM];
__device__ int   g_bh[NHYP];

// ---------------- batch id dtype detect + convert ----------------
__global__ void conv_batch(const void* bpr, const void* bhr, int n) {
    __shared__ int s_is64;
    if (threadIdx.x == 0) {
        const int* w = (const int*)bhr;
        int z = 0;
        for (int i = 0; i < 32; i++) {
            int idx = n / 2 + 2 * i + 1;
            if (w[idx] == 0) z++;
        }
        s_is64 = (z > 16) ? 1 : 0;
    }
    __syncthreads();
    int is64 = s_is64;
    const int* bp32 = (const int*)bpr;
    const int* bh32 = (const int*)bhr;
    for (int i = threadIdx.x; i < n; i += blockDim.x) {
        g_bp[i] = is64 ? bp32[2 * i] : bp32[i];
        g_bh[i] = is64 ? bh32[2 * i] : bh32[i];
    }
}

// ---------------- tf32 helpers ----------------
__device__ __forceinline__ uint32_t f2tf32(float f) {
    uint32_t u;
    asm("cvt.rna.tf32.f32 %0, %1;" : "=r"(u) : "f"(f));
    return u;
}

__device__ __forceinline__ void mma_tf32(float c[4], const uint32_t a[4], const uint32_t b[2]) {
    asm volatile(
        "mma.sync.aligned.m16n8k8.row.col.f32.tf32.tf32.f32 "
        "{%0,%1,%2,%3}, {%4,%5,%6,%7}, {%8,%9}, {%0,%1,%2,%3};\n"
        : "+f"(c[0]), "+f"(c[1]), "+f"(c[2]), "+f"(c[3])
        : "r"(a[0]), "r"(a[1]), "r"(a[2]), "r"(a[3]), "r"(b[0]), "r"(b[1]));
}

__device__ __forceinline__ void cp16(uint32_t saddr, const void* gaddr) {
    asm volatile("cp.async.cg.shared.global [%0], [%1], 16;"
                 :: "r"(saddr), "l"(gaddr) : "memory");
}

// ---------------- tf32 tensor-core GEMM ----------------
// CTA tile 128x128, BK=16, 8 warps each 64x32.
// EPI: 0 plain(+bias, col guard); 1 q/k head-permute store as tf32 bits (+bias);
//      2 gelu(+bias); 4 plain store as tf32 bits (+bias, col guard)
template <int EPI, int TB>
__global__ __launch_bounds__(256) void mma_gemm(
    const float* __restrict__ A, int lda, size_t sA,
    const float* __restrict__ B, int ldb, size_t sB,
    const float* __restrict__ bias,
    float* __restrict__ C, int ldc, size_t sC,
    int M, int K, int Nreal)
{
    A += (size_t)blockIdx.z * sA;
    B += (size_t)blockIdx.z * sB;
    C += (size_t)blockIdx.z * sC;

    __shared__ uint32_t As[16][140];
    __shared__ uint32_t Bs[16][140];

    int tid = threadIdx.x;
    int i0 = blockIdx.y * 128;
    int j0 = blockIdx.x * 128;
    int w = tid >> 5, lane = tid & 31;
    int g = lane >> 2, tg = lane & 3;
    int wm = (w >> 2) * 64;
    int wn = (w & 3) * 32;

    float acc[4][4][4];
#pragma unroll
    for (int i = 0; i < 4; i++)
#pragma unroll
        for (int j = 0; j < 4; j++)
#pragma unroll
            for (int v = 0; v < 4; v++) acc[i][j][v] = 0.f;

    int amr = tid >> 2;
    int akc = (tid & 3) * 4;
    int bkr = tid >> 5;
    int bnc = (tid & 31) * 4;

    float4 a_reg[2], b_reg[2];
    int ntile = K / 16;

    {
        int k0 = 0;
#pragma unroll
        for (int l = 0; l < 2; l++) {
            a_reg[l] = *(const float4*)&A[(size_t)(i0 + amr + l * 64) * lda + k0 + akc];
            if (TB == 0) {
                int n = j0 + bnc;
                if (n < Nreal)
                    b_reg[l] = *(const float4*)&B[(size_t)(k0 + bkr + l * 8) * ldb + n];
                else
                    b_reg[l] = make_float4(0.f, 0.f, 0.f, 0.f);
            } else {
                int n = j0 + amr + l * 64;
                if (n < Nreal)
                    b_reg[l] = *(const float4*)&B[(size_t)n * ldb + k0 + akc];
                else
                    b_reg[l] = make_float4(0.f, 0.f, 0.f, 0.f);
            }
        }
    }

    for (int t = 0; t < ntile; t++) {
#pragma unroll
        for (int l = 0; l < 2; l++) {
            int m = amr + l * 64;
            As[akc + 0][m] = f2tf32(a_reg[l].x);
            As[akc + 1][m] = f2tf32(a_reg[l].y);
            As[akc + 2][m] = f2tf32(a_reg[l].z);
            As[akc + 3][m] = f2tf32(a_reg[l].w);
            if (TB == 0) {
                uint4 tb;
                tb.x = f2tf32(b_reg[l].x); tb.y = f2tf32(b_reg[l].y);
                tb.z = f2tf32(b_reg[l].z); tb.w = f2tf32(b_reg[l].w);
                *(uint4*)&Bs[bkr + l * 8][bnc] = tb;
            } else {
                int n = amr + l * 64;
                Bs[akc + 0][n] = f2tf32(b_reg[l].x);
                Bs[akc + 1][n] = f2tf32(b_reg[l].y);
                Bs[akc + 2][n] = f2tf32(b_reg[l].z);
                Bs[akc + 3][n] = f2tf32(b_reg[l].w);
            }
        }
        __syncthreads();

        if (t + 1 < ntile) {
            int k0 = (t + 1) * 16;
#pragma unroll
            for (int l = 0; l < 2; l++) {
                a_reg[l] = *(const float4*)&A[(size_t)(i0 + amr + l * 64) * lda + k0 + akc];
                if (TB == 0) {
                    int n = j0 + bnc;
                    if (n < Nreal)
                        b_reg[l] = *(const float4*)&B[(size_t)(k0 + bkr + l * 8) * ldb + n];
                    else
                        b_reg[l] = make_float4(0.f, 0.f, 0.f, 0.f);
                } else {
                    int n = j0 + amr + l * 64;
                    if (n < Nreal)
                        b_reg[l] = *(const float4*)&B[(size_t)n * ldb + k0 + akc];
                    else
                        b_reg[l] = make_float4(0.f, 0.f, 0.f, 0.f);
                }
            }
        }

#pragma unroll
        for (int ks = 0; ks < 2; ks++) {
            int kk = ks * 8;
            uint32_t af[4][4], bf[4][2];
#pragma unroll
            for (int mt = 0; mt < 4; mt++) {
                int m0 = wm + mt * 16;
                af[mt][0] = As[kk + tg][m0 + g];
                af[mt][1] = As[kk + tg][m0 + g + 8];
                af[mt][2] = As[kk + tg + 4][m0 + g];
                af[mt][3] = As[kk + tg + 4][m0 + g + 8];
            }
#pragma unroll
            for (int nt = 0; nt < 4; nt++) {
                int n0 = wn + nt * 8;
                bf[nt][0] = Bs[kk + tg][n0 + g];
                bf[nt][1] = Bs[kk + tg + 4][n0 + g];
            }
#pragma unroll
            for (int mt = 0; mt < 4; mt++)
#pragma unroll
                for (int nt = 0; nt < 4; nt++)
                    mma_tf32(acc[mt][nt], af[mt], bf[nt]);
        }
        __syncthreads();
    }

#pragma unroll
    for (int mt = 0; mt < 4; mt++) {
        int r0 = i0 + wm + mt * 16 + g;
#pragma unroll
        for (int nt = 0; nt < 4; nt++) {
            int c0 = j0 + wn + nt * 8 + 2 * tg;
#pragma unroll
            for (int v = 0; v < 4; v++) {
                int r = r0 + (v >> 1) * 8;
                int c = c0 + (v & 1);
                float val = acc[mt][nt][v];
                if (EPI == 1) {
                    val += bias[c];
                    *(uint32_t*)&C[(((size_t)(c & 3) * M) + r) * ATND + (c >> 2)] = f2tf32(val);
                } else if (EPI == 4) {
                    if (c < Nreal) {
                        val += bias[c];
                        *(uint32_t*)&C[(size_t)r * ldc + c] = f2tf32(val);
                    }
                } else {
                    if (c < Nreal) {
                        if (bias) val += bias[c];
                        if (EPI == 2)
                            val = 0.5f * val * (1.0f + erff(val * 0.70710678118654752f));
                        C[(size_t)r * ldc + c] = val;
                    }
                }
            }
        }
    }
}

// ---------------- fused flash attention ----------------
// grid (NHYP/128, NHEAD), 256 threads (8 warps x 16 q-rows).
// smem words: Qs[128*132] @0 | Ks[2][32*132] @16896 | Vs[2][32*200] @25344 | bp[2][32] @38144
#define FA_SMEM_BYTES ((38144 + 64) * 4)

__global__ __launch_bounds__(256, 1) void flash_attn()
{
    extern __shared__ uint32_t su[];
    const int tid = threadIdx.x;
    const int w = tid >> 5, lane = tid & 31;
    const int g = lane >> 2, tg = lane & 3;
    const int i0 = blockIdx.x * 128;
    const int h  = blockIdx.y;
    const int wm = w * 16;

    const uint32_t* gQ  = (const uint32_t*)g_Qp + ((size_t)h * NHYP + i0) * ATND;
    const uint32_t* gK0 = (const uint32_t*)g_Kp + (size_t)h * NPREM * ATND;
    const uint32_t* gV0 = (const uint32_t*)g_V + h * 192;

    uint32_t sbase = (uint32_t)__cvta_generic_to_shared(su);
    int* sbp = (int*)(su + 38144);

    // Q tile 128x128 (tf32 bits), stride 132
#pragma unroll
    for (int i = 0; i < 16; i++) {
        int flat = i * 256 + tid;
        int row = flat >> 5, ch = (flat & 31) * 4;
        *(uint4*)&su[row * 132 + ch] = *(const uint4*)&gQ[row * 128 + ch];
    }

    // prefetch premise tile 0
    {
        int ch = (tid & 31) * 4;
#pragma unroll
        for (int r = 0; r < 4; r++) {
            int row = r * 8 + w;
            cp16(sbase + (16896 + row * 132 + ch) * 4, gK0 + (size_t)row * 128 + ch);
        }
#pragma unroll
        for (int i = 0; i < 6; i++) {
            int flat = i * 256 + tid;
            int row = flat / 48, vc = (flat % 48) * 4;
            cp16(sbase + (25344 + row * 200 + vc) * 4, gV0 + (size_t)row * 768 + vc);
        }
        if (tid < 32) sbp[tid] = g_bp[tid];
        asm volatile("cp.async.commit_group;" ::: "memory");
    }

    const int brow0 = g_bh[i0 + wm + g];
    const int brow1 = g_bh[i0 + wm + g + 8];

    float o[24][4];
#pragma unroll
    for (int nt = 0; nt < 24; nt++) { o[nt][0] = o[nt][1] = o[nt][2] = o[nt][3] = 0.f; }
    float mr0 = -INFINITY, mr1 = -INFINITY, lr0 = 0.f, lr1 = 0.f;

    const int NT = NPREM / 32;
    for (int t = 0; t < NT; t++) {
        int buf = t & 1;
        if (t + 1 < NT) {
            int nbuf = buf ^ 1;
            int m0n = (t + 1) * 32;
            const uint32_t* gK = gK0 + (size_t)m0n * 128;
            int ch = (tid & 31) * 4;
#pragma unroll
            for (int r = 0; r < 4; r++) {
                int row = r * 8 + w;
                cp16(sbase + (16896 + nbuf * 4224 + row * 132 + ch) * 4,
                     gK + (size_t)row * 128 + ch);
            }
#pragma unroll
            for (int i = 0; i < 6; i++) {
                int flat = i * 256 + tid;
                int row = flat / 48, vc = (flat % 48) * 4;
                cp16(sbase + (25344 + nbuf * 6400 + row * 200 + vc) * 4,
                     gV0 + (size_t)(m0n + row) * 768 + vc);
            }
            if (tid < 32) sbp[nbuf * 32 + tid] = g_bp[m0n + tid];
            asm volatile("cp.async.commit_group;" ::: "memory");
            asm volatile("cp.async.wait_group 1;" ::: "memory");
        } else {
            asm volatile("cp.async.wait_group 0;" ::: "memory");
        }
        __syncthreads();

        const uint32_t* Kb = su + 16896 + buf * 4224;
        const uint32_t* Vb = su + 25344 + buf * 6400;
        const int* bpb = sbp + buf * 32;

        // S = Q K^T for 128 q-rows x 32 premise cols
        float sv[4][4];
#pragma unroll
        for (int nt = 0; nt < 4; nt++) sv[nt][0] = sv[nt][1] = sv[nt][2] = sv[nt][3] = 0.f;
#pragma unroll
        for (int ks = 0; ks < 16; ks++) {
            int kk = ks * 8;
            uint32_t a[4];
            a[0] = su[(wm + g) * 132 + kk + tg];
            a[1] = su[(wm + g + 8) * 132 + kk + tg];
            a[2] = su[(wm + g) * 132 + kk + tg + 4];
            a[3] = su[(wm + g + 8) * 132 + kk + tg + 4];
#pragma unroll
            for (int nt = 0; nt < 4; nt++) {
                uint32_t b[2];
                b[0] = Kb[(nt * 8 + g) * 132 + kk + tg];
                b[1] = Kb[(nt * 8 + g) * 132 + kk + tg + 4];
                mma_tf32(sv[nt], a, b);
            }
        }

        // scale + mask + row max
        const float SC = 0.08838834764831845f;
        float tm0 = -INFINITY, tm1 = -INFINITY;
#pragma unroll
        for (int nt = 0; nt < 4; nt++) {
            int c0 = nt * 8 + 2 * tg;
            int b0 = bpb[c0], b1 = bpb[c0 + 1];
            sv[nt][0] = (b0 == brow0) ? -1e10f : sv[nt][0] * SC;
            sv[nt][1] = (b1 == brow0) ? -1e10f : sv[nt][1] * SC;
            sv[nt][2] = (b0 == brow1) ? -1e10f : sv[nt][2] * SC;
            sv[nt][3] = (b1 == brow1) ? -1e10f : sv[nt][3] * SC;
            tm0 = fmaxf(tm0, fmaxf(sv[nt][0], sv[nt][1]));
            tm1 = fmaxf(tm1, fmaxf(sv[nt][2], sv[nt][3]));
        }
        tm0 = fmaxf(tm0, __shfl_xor_sync(0xffffffffu, tm0, 1));
        tm0 = fmaxf(tm0, __shfl_xor_sync(0xffffffffu, tm0, 2));
        tm1 = fmaxf(tm1, __shfl_xor_sync(0xffffffffu, tm1, 1));
        tm1 = fmaxf(tm1, __shfl_xor_sync(0xffffffffu, tm1, 2));

        float mn0 = fmaxf(mr0, tm0), mn1 = fmaxf(mr1, tm1);
        float al0 = __expf(mr0 - mn0), al1 = __expf(mr1 - mn1);
        mr0 = mn0; mr1 = mn1;

        float ts0 = 0.f, ts1 = 0.f;
#pragma unroll
        for (int nt = 0; nt < 4; nt++) {
            sv[nt][0] = __expf(sv[nt][0] - mn0);
            sv[nt][1] = __expf(sv[nt][1] - mn0);
            sv[nt][2] = __expf(sv[nt][2] - mn1);
            sv[nt][3] = __expf(sv[nt][3] - mn1);
            ts0 += sv[nt][0] + sv[nt][1];
            ts1 += sv[nt][2] + sv[nt][3];
        }
        ts0 += __shfl_xor_sync(0xffffffffu, ts0, 1);
        ts0 += __shfl_xor_sync(0xffffffffu, ts0, 2);
        ts1 += __shfl_xor_sync(0xffffffffu, ts1, 1);
        ts1 += __shfl_xor_sync(0xffffffffu, ts1, 2);
        lr0 = lr0 * al0 + ts0;
        lr1 = lr1 * al1 + ts1;

        if (!__all_sync(0xffffffffu, (al0 == 1.f) && (al1 == 1.f))) {
#pragma unroll
            for (int nt = 0; nt < 24; nt++) {
                o[nt][0] *= al0; o[nt][1] *= al0;
                o[nt][2] *= al1; o[nt][3] *= al1;
            }
        }

        // O += P @ V : transpose P C-frags -> A-frags via shuffles
#pragma unroll
        for (int kt = 0; kt < 4; kt++) {
            uint32_t c0 = f2tf32(sv[kt][0]), c1 = f2tf32(sv[kt][1]);
            uint32_t c2 = f2tf32(sv[kt][2]), c3 = f2tf32(sv[kt][3]);
            int srcA = 4 * g + (tg >> 1);
            int srcB = srcA + 2;
            uint32_t t0 = __shfl_sync(0xffffffffu, c0, srcA);
            uint32_t t1 = __shfl_sync(0xffffffffu, c1, srcA);
            uint32_t t2 = __shfl_sync(0xffffffffu, c0, srcB);
            uint32_t t3 = __shfl_sync(0xffffffffu, c1, srcB);
            uint32_t t4 = __shfl_sync(0xffffffffu, c2, srcA);
            uint32_t t5 = __shfl_sync(0xffffffffu, c3, srcA);
            uint32_t t6 = __shfl_sync(0xffffffffu, c2, srcB);
            uint32_t t7 = __shfl_sync(0xffffffffu, c3, srcB);
            bool odd = tg & 1;
            uint32_t a[4];
            a[0] = odd ? t1 : t0;   // P[g][tg]
            a[1] = odd ? t5 : t4;   // P[g+8][tg]
            a[2] = odd ? t3 : t2;   // P[g][tg+4]
            a[3] = odd ? t7 : t6;   // P[g+8][tg+4]
#pragma unroll
            for (int nt = 0; nt < 24; nt++) {
                uint32_t b[2];
                b[0] = Vb[(kt * 8 + tg) * 200 + nt * 8 + g];
                b[1] = Vb[(kt * 8 + tg + 4) * 200 + nt * 8 + g];
                mma_tf32(o[nt], a, b);
            }
        }
        __syncthreads();
    }

    float inv0 = 1.f / lr0, inv1 = 1.f / lr1;
    int r0 = i0 + wm + g, r1 = r0 + 8;
#pragma unroll
    for (int nt = 0; nt < 24; nt++) {
        int c = h * 192 + nt * 8 + 2 * tg;
        *(float2*)&g_att[(size_t)r0 * BD + c] = make_float2(o[nt][0] * inv0, o[nt][1] * inv0);
        *(float2*)&g_att[(size_t)r1 * BD + c] = make_float2(o[nt][2] * inv1, o[nt][3] * inv1);
    }
}

// ---------------- warp reductions ----------------
__device__ __forceinline__ float warpSum(float v) {
#pragma unroll
    for (int of = 16; of; of >>= 1) v += __shfl_xor_sync(0xffffffffu, v, of);
    return v;
}

// ---------------- feats = concat(ctx_h, lhs_h - attended) ----------------
__global__ void build_feats(const float* __restrict__ ctx_h, const float* __restrict__ lhs_h)
{
    size_t idx = (size_t)blockIdx.x * blockDim.x + threadIdx.x;
    if (idx >= (size_t)NHYP * FEAT) return;
    int n = (int)(idx / FEAT);
    int j = (int)(idx % FEAT);
    float v;
    if (j < DIM) v = ctx_h[(size_t)n * DIM + j];
    else {
        int jj = j - DIM;
        v = lhs_h[(size_t)n * BD + jj] - g_att[(size_t)n * BD + jj];
    }
    g_feats[idx] = v;
}

// ---------------- layernorm(128) in place ----------------
__global__ __launch_bounds__(128) void layernorm_inplace(
    float* __restrict__ X, const float* __restrict__ gw, const float* __restrict__ gb)
{
    int n = blockIdx.x;
    int d = threadIdx.x;
    float v = X[(size_t)n * 128 + d];
    __shared__ float sred[4];
    __shared__ float sbc;
    int lane = d & 31, wid = d >> 5;

    float s = warpSum(v);
    if (lane == 0) sred[wid] = s;
    __syncthreads();
    if (wid == 0) {
        float x = (lane < 4) ? sred[lane] : 0.f;
        x = warpSum(x);
        if (lane == 0) sbc = x;
    }
    __syncthreads();
    float mu = sbc * (1.0f / 128.0f);
    float dv = v - mu;

    float s2 = warpSum(dv * dv);
    if (lane == 0) sred[wid] = s2;
    __syncthreads();
    if (wid == 0) {
        float x = (lane < 4) ? sred[lane] : 0.f;
        x = warpSum(x);
        if (lane == 0) sbc = x;
    }
    __syncthreads();
    float var = sbc * (1.0f / 128.0f);
    X[(size_t)n * 128 + d] = dv * rsqrtf(var + 1e-5f) * gw[d] + gb[d];
}

// ---------------- segment mean pool + classifier ----------------
__global__ __launch_bounds__(128) void pool_classify(
    const float* __restrict__ H2, const float* __restrict__ Wc,
    const float* __restrict__ bc, float* __restrict__ out)
{
    int b = blockIdx.x;
    int d = threadIdx.x;

    int l = 0, r = NHYP;
    while (l < r) { int m = (l + r) >> 1; if (g_bh[m] < b) l = m + 1; else r = m; }
    int s0 = l;
    l = s0; r = NHYP;
    while (l < r) { int m = (l + r) >> 1; if (g_bh[m] < b + 1) l = m + 1; else r = m; }
    int e0 = l;

    float sum = 0.f;
    for (int n = s0; n < e0; n++) sum += H2[(size_t)n * 128 + d];
    float cnt = (float)(e0 - s0);
    float pooled = sum / fmaxf(cnt, 1.0f);

    __shared__ float sp[128];
    sp[d] = pooled;
    __syncthreads();
    if (d < 3) {
        float o = bc[d];
        for (int k = 0; k < 128; k++) o = fmaf(sp[k], Wc[k * 3 + d], o);
        out[b * 3 + d] = o;
    }
}

// ---------------- host launch ----------------
extern "C" void kernel_launch(void* const* d_in, const int* in_sizes, int n_in,
                              void* d_out, int out_size)
{
    const float* ctx_p = (const float*)d_in[0];
    const float* ctx_h = (const float*)d_in[1];
    const float* lhs_p = (const float*)d_in[2];
    const float* lhs_h = (const float*)d_in[3];
    const void*  batch_p = d_in[4];
    const void*  batch_h = d_in[5];
    const float* Wq = (const float*)d_in[6];
    const float* bq = (const float*)d_in[7];
    const float* Wk = (const float*)d_in[8];
    const float* bk = (const float*)d_in[9];
    const float* Wv = (const float*)d_in[10];
    const float* bv = (const float*)d_in[11];
    const float* W1 = (const float*)d_in[12];
    const float* b1 = (const float*)d_in[13];
    const float* W2 = (const float*)d_in[14];
    const float* ln_g = (const float*)d_in[15];
    const float* ln_b = (const float*)d_in[16];
    const float* Wc = (const float*)d_in[17];
    const float* bc = (const float*)d_in[18];
    float* out = (float*)d_out;

    float *Qp, *Kp, *V, *F, *H1, *H2;
    cudaGetSymbolAddress((void**)&Qp, g_Qp);
    cudaGetSymbolAddress((void**)&Kp, g_Kp);
    cudaGetSymbolAddress((void**)&V, g_V);
    cudaGetSymbolAddress((void**)&F, g_feats);
    cudaGetSymbolAddress((void**)&H1, g_h1);
    cudaGetSymbolAddress((void**)&H2, g_h2);

    static int fa_attr_done = 0;
    if (!fa_attr_done) {
        cudaFuncSetAttribute(flash_attn, cudaFuncAttributeMaxDynamicSharedMemorySize,
                             FA_SMEM_BYTES);
        fa_attr_done = 1;
    }

    conv_batch<<<1, 256>>>(batch_p, batch_h, NPREM);

    // projections (store tf32 bits)
    mma_gemm<1, 0><<<dim3(4, 32), 256>>>(ctx_h, DIM, 0, Wq, DIM, 0, bq,
                                         Qp, 0, 0, NHYP, DIM, DIM);
    mma_gemm<1, 0><<<dim3(4, 32), 256>>>(ctx_p, DIM, 0, Wk, DIM, 0, bk,
                                         Kp, 0, 0, NPREM, DIM, DIM);
    mma_gemm<4, 0><<<dim3(6, 32), 256>>>(lhs_p, BD, 0, Wv, BD, 0, bv,
                                         V, BD, 0, NPREM, BD, BD);

    // fused attention
    flash_attn<<<dim3(NHYP / 128, NHEAD), 256, FA_SMEM_BYTES>>>();

    // mlp
    {
        size_t total = (size_t)NHYP * FEAT;
        int thr = 256;
        int blk = (int)((total + thr - 1) / thr);
        build_feats<<<blk, thr>>>(ctx_h, lhs_h);
    }
    mma_gemm<2, 0><<<dim3(2, 32), 256>>>(F, FEAT, 0, W1, 256, 0, b1,
                                         H1, 256, 0, NHYP, FEAT, 256);
    mma_gemm<0, 0><<<dim3(1, 32), 256>>>(H1, 256, 0, W2, 128, 0,
                                         (const float*)nullptr,
                                         H2, 128, 0, NHYP, 256, 128);
    layernorm_inplace<<<NHYP, 128>>>(H2, ln_g, ln_b);

    pool_classify<<<NB, 128>>>(H2, Wc, bc, out);

    (void)in_sizes; (void)n_in; (void)out_size;
}